// round 15
// baseline (speedup 1.0000x reference)
#include <cuda_runtime.h>
#include <cuda_fp16.h>
#include <cstdint>

#define NN    4096
#define DD    128
#define TWO_N 8192
#define ZC    256
#define KSPLIT 4
#define KPER  (NN / KSPLIT)      // 1024 per CTA
#define KC    64
#define NCHC  (KPER / KC)        // 16 chunks per CTA
#define NCH_ALL (NN / KC)        // 64 chunks total
#define BSTG  16384              // B stage: 64x128 fp16
#define STG   17408              // B + 1KB mask
#define STAGES 4
#define SMEM_GEMM (STAGES * STG) // 69632 -> 2 CTAs/SM
#define SMEM_XWM  65536          // x tile 32K + W tile 32K

// ------------------------- device scratch -------------------------
__device__ __align__(16) unsigned g_maskT[(size_t)NCH_ALL * NN * 2]; // 2 MB [chunk][row][2w]
__device__ __align__(16) __half g_Zh[(size_t)NN * ZC];               // 2 MB [K][N]
__device__ __align__(16) float g_XW[(size_t)TWO_N * DD];             // 4 MB
__device__ __align__(16) float g_Yp[KSPLIT][(size_t)NN * ZC];        // 16 MB partials
__device__ float g_s[NN];
__device__ float g_stats[2 * DD];

// ------------------------- PTX helpers ----------------------------
__device__ __forceinline__ uint32_t smem_u32(const void* p) {
    uint32_t a;
    asm("{ .reg .u64 t; cvta.to.shared.u64 t, %1; cvt.u32.u64 %0, t; }" : "=r"(a) : "l"(p));
    return a;
}
#define CP16(dst, src) asm volatile("cp.async.cg.shared.global [%0], [%1], 16;" :: "r"(dst), "l"(src))
#define CP8(dst, src)  asm volatile("cp.async.ca.shared.global [%0], [%1], 8;"  :: "r"(dst), "l"(src))
#define CP_COMMIT()    asm volatile("cp.async.commit_group;" ::: "memory")
#define CP_WAITN(n)    asm volatile("cp.async.wait_group %0;" :: "n"(n) : "memory")

#define LDSM4(r, a)  asm volatile("ldmatrix.sync.aligned.m8n8.x4.shared.b16 {%0,%1,%2,%3}, [%4];" \
    : "=r"((r)[0]),"=r"((r)[1]),"=r"((r)[2]),"=r"((r)[3]) : "r"(a))
#define LDSM4T(r, a) asm volatile("ldmatrix.sync.aligned.m8n8.x4.trans.shared.b16 {%0,%1,%2,%3}, [%4];" \
    : "=r"((r)[0]),"=r"((r)[1]),"=r"((r)[2]),"=r"((r)[3]) : "r"(a))

#define MMA(d, a, b0_, b1_) asm volatile( \
    "mma.sync.aligned.m16n8k16.row.col.f32.f16.f16.f32 " \
    "{%0,%1,%2,%3},{%4,%5,%6,%7},{%8,%9},{%0,%1,%2,%3};" \
    : "+f"((d)[0]),"+f"((d)[1]),"+f"((d)[2]),"+f"((d)[3]) \
    : "r"((a)[0]),"r"((a)[1]),"r"((a)[2]),"r"((a)[3]), "r"(b0_), "r"(b1_))

// 2 bits -> packed fp16x2 (bit0 -> low half, bit1 -> high half), 1.0 or 0.0
__device__ __forceinline__ uint32_t lut2(unsigned e) {
    return ((e & 1u) ? 0x3C00u : 0u) | ((e & 2u) ? 0x3C000000u : 0u);
}
__device__ __forceinline__ uint32_t pack_h2(float a, float b) {
    return (uint32_t)__half_as_ushort(__float2half_rn(a))
         | ((uint32_t)__half_as_ushort(__float2half_rn(b)) << 16);
}

// ---------------------------------------------------------------------------
// K1: binarize A -> transposed bitmask [chunk][row][2 words]; rowsum -> s.
// ---------------------------------------------------------------------------
__global__ void k_prep(const float* __restrict__ A) {
    int row = blockIdx.x, t = threadIdx.x, w = t >> 5, l = t & 31;
    __shared__ int scnt[4];
    if (row == 0 && t < 128) { g_stats[t] = 0.0f; g_stats[128 + t] = 0.0f; }
    const float* ar = A + (size_t)row * NN;
    int cnt = 0;
    #pragma unroll 4
    for (int it = 0; it < 32; ++it) {
        float v = ar[it * 128 + t];
        bool b = (v > 0.0f);
        unsigned bal = __ballot_sync(0xffffffffu, b);
        cnt += b ? 1 : 0;
        if (l == 0) {
            int W = it * 4 + w;                      // 32-col word index 0..127
            g_maskT[((size_t)(W >> 1) * NN + row) * 2 + (W & 1)] = bal;
        }
    }
    #pragma unroll
    for (int o = 16; o; o >>= 1) cnt += __shfl_down_sync(0xffffffffu, cnt, o);
    if (l == 0) scnt[w] = cnt;
    __syncthreads();
    if (t == 0)
        g_s[row] = rsqrtf((float)(scnt[0] + scnt[1] + scnt[2] + scnt[3] + 1));
}

// ---------------------------------------------------------------------------
// K2: xw = x@W on tensor cores, fused Z build (round-13 proven).
// ---------------------------------------------------------------------------
__global__ void __launch_bounds__(256) k_xwm(const float* __restrict__ x,
                                             const float* __restrict__ W) {
    extern __shared__ char smem[];
    uint32_t sb = smem_u32(smem);          // [0,32768) x-tile, [32768,65536) W-tile
    int t = threadIdx.x, wid = t >> 5, lid = t & 31;
    int rbase = blockIdx.x * 128;

    #pragma unroll
    for (int p = 0; p < 16; ++p) {
        int idx = t + p * 256;
        int r = idx >> 5, k4 = idx & 31;
        float4 v = *(const float4*)&x[(size_t)(rbase + r) * DD + k4 * 4];
        uint2 pk = make_uint2(pack_h2(v.x, v.y), pack_h2(v.z, v.w));
        uint32_t off = (uint32_t)(r * 256 + (((k4 >> 1) ^ (r & 7)) << 4) + (k4 & 1) * 8);
        *(uint2*)(smem + off) = pk;
    }
    #pragma unroll
    for (int p = 0; p < 16; ++p) {
        int idx = t + p * 256;
        int k = idx >> 5, n4 = idx & 31;
        float4 v = *(const float4*)&W[(size_t)k * DD + n4 * 4];
        uint2 pk = make_uint2(pack_h2(v.x, v.y), pack_h2(v.z, v.w));
        uint32_t off = (uint32_t)(32768 + k * 256 + (((n4 >> 1) ^ (k & 7)) << 4) + (n4 & 1) * 8);
        *(uint2*)(smem + off) = pk;
    }
    __syncthreads();

    int m0 = wid * 16;
    float acc[16][4];
    #pragma unroll
    for (int nj = 0; nj < 16; ++nj)
        #pragma unroll
        for (int q = 0; q < 4; ++q) acc[nj][q] = 0.0f;

    #pragma unroll
    for (int kk = 0; kk < 8; ++kk) {
        uint32_t af[4];
        int arow = m0 + (lid & 15);
        int ach  = kk * 2 + (lid >> 4);
        LDSM4(af, sb + arow * 256 + ((ach ^ (arow & 7)) << 4));
        int kb = kk * 16 + (lid & 15);
        int cb = lid >> 4;
        #pragma unroll
        for (int g = 0; g < 4; ++g) {
            uint32_t bf[4][2];
            #pragma unroll
            for (int np = 0; np < 2; ++np) {
                int ch = g * 4 + np * 2 + cb;
                uint32_t r4[4];
                LDSM4T(r4, sb + 32768 + kb * 256 + ((ch ^ (kb & 7)) << 4));
                bf[np*2][0]=r4[0]; bf[np*2][1]=r4[1];
                bf[np*2+1][0]=r4[2]; bf[np*2+1][1]=r4[3];
            }
            #pragma unroll
            for (int nj = 0; nj < 4; ++nj)
                MMA(acc[g * 4 + nj], af, bf[nj][0], bf[nj][1]);
        }
    }

    int grp = lid >> 2, qp = lid & 3;
    int gr0 = rbase + m0 + grp;
    int gr1 = gr0 + 8;
    int top0 = (gr0 < NN);
    int j0 = top0 ? gr0 : (gr0 - NN);
    int j1 = top0 ? gr1 : (gr1 - NN);
    float s0 = g_s[j0], s1 = g_s[j1];
    int cof = top0 ? 0 : DD;
    #pragma unroll
    for (int nj = 0; nj < 16; ++nj) {
        int c = nj * 8 + qp * 2;
        *(float2*)&g_XW[(size_t)gr0 * DD + c] = make_float2(acc[nj][0], acc[nj][1]);
        *(float2*)&g_XW[(size_t)gr1 * DD + c] = make_float2(acc[nj][2], acc[nj][3]);
        *(uint32_t*)&g_Zh[(size_t)j0 * ZC + cof + c] = pack_h2(s0 * acc[nj][0], s0 * acc[nj][1]);
        *(uint32_t*)&g_Zh[(size_t)j1 * ZC + cof + c] = pack_h2(s1 * acc[nj][2], s1 * acc[nj][3]);
    }
}

// ---------------------------------------------------------------------------
// K3: GEMM partials (round-13 proven shape). grid (32, 2, 4): CTA 128x128,
// K-split/4 on grid.z (1024 K, 16 chunks). 8 warps, warp tile 16x128.
// 4-stage cp.async, one barrier per chunk, 2 CTAs/SM. z==0 CTAs fold the
// diag term s_i*XW into their partial (epilogue kernel needs no XW read).
// ---------------------------------------------------------------------------
__global__ void __launch_bounds__(256, 2) k_gemm() {
    extern __shared__ char smem[];
    uint32_t sb = smem_u32(smem);
    int t = threadIdx.x, wid = t >> 5, lid = t & 31;
    int m0 = wid * 16;
    int mbase = blockIdx.x * 128;
    int nbg   = blockIdx.y * 128;
    const __half* Bg = g_Zh + (size_t)(blockIdx.z * KPER) * ZC + nbg;
    const unsigned* Mg = g_maskT + ((size_t)(blockIdx.z * NCHC) * NN + mbase) * 2;

    auto issue = [&](int c) {
        if (c < NCHC) {
            uint32_t sa = sb + (c % STAGES) * STG;
            #pragma unroll
            for (int p = 0; p < 4; ++p) {            // B: 64x128 fp16, 256B rows
                int idx = t + p * 256;
                int k = idx >> 4, ch = idx & 15;
                uint32_t off = k * 256 + ((ch ^ (k & 7)) << 4);
                CP16(sa + off, (const char*)(Bg + (size_t)(c * KC + k) * ZC + ch * 8));
            }
            if (t < 128)                              // mask: 128 rows x 8B
                CP8(sa + BSTG + t * 8, (const char*)(Mg + (size_t)c * NN * 2 + t * 2));
        }
        CP_COMMIT();
    };

    float acc[16][4];
    #pragma unroll
    for (int nj = 0; nj < 16; ++nj)
        #pragma unroll
        for (int q = 0; q < 4; ++q) acc[nj][q] = 0.0f;

    issue(0); issue(1); issue(2);

    int ra = lid >> 2;
    int c0 = (lid & 3) * 2;

    for (int c = 0; c < NCHC; ++c) {
        CP_WAITN(2);                 // chunk c resident (<=2 groups pending)
        __syncthreads();             // all warps done with stage (c-1)%4
        issue(c + 3);                // refills stage (c+3)%4 == (c-1)%4
        uint32_t sa = sb + (c % STAGES) * STG;
        const uint2* maskS = (const uint2*)(smem + (c % STAGES) * STG + BSTG);

        uint2 mw0 = maskS[m0 + ra];      // row m0+ra of my strip
        uint2 mw1 = maskS[m0 + ra + 8];  // row m0+ra+8

        #pragma unroll
        for (int kk = 0; kk < 4; ++kk) {
            int kb = kk * 16 + (lid & 15);
            int cb = lid >> 4;
            int sh = ((kk & 1) << 4) + c0;
            unsigned ta = ((kk < 2) ? mw0.x : mw0.y) >> sh;
            unsigned tb = ((kk < 2) ? mw1.x : mw1.y) >> sh;
            uint32_t af[4];
            af[0] = lut2(ta & 3u);           // (ra,   c0..c0+1)
            af[1] = lut2(tb & 3u);           // (ra+8, c0..c0+1)
            af[2] = lut2((ta >> 8) & 3u);    // (ra,   c0+8..c0+9)
            af[3] = lut2((tb >> 8) & 3u);    // (ra+8, c0+8..c0+9)
            #pragma unroll
            for (int g = 0; g < 4; ++g) {            // 4 groups of 32 cols
                uint32_t bf[4][2];
                #pragma unroll
                for (int np = 0; np < 2; ++np) {
                    int ch = g * 4 + np * 2 + cb;    // 16B column-chunk index
                    uint32_t r4[4];
                    LDSM4T(r4, sa + kb * 256 + ((ch ^ (kb & 7)) << 4));
                    bf[np*2][0]=r4[0]; bf[np*2][1]=r4[1];
                    bf[np*2+1][0]=r4[2]; bf[np*2+1][1]=r4[3];
                }
                #pragma unroll
                for (int nj = 0; nj < 4; ++nj)
                    MMA(acc[g * 4 + nj], af, bf[nj][0], bf[nj][1]);
            }
        }
    }

    // epilogue: z==0 folds diag term s_i * XW[drow][oc] into the partial
    int grp = lid >> 2, qp = lid & 3;
    int r0 = mbase + m0 + grp;
    int r1 = r0 + 8;
    if (blockIdx.z == 0) {
        float s0 = g_s[r0], s1 = g_s[r1];
        #pragma unroll
        for (int nj = 0; nj < 16; ++nj) {
            int C = nbg + nj * 8 + qp * 2;
            int oc  = (C < DD) ? C : (C - DD);
            int dr0 = (C < DD) ? (NN + r0) : r0;
            int dr1 = (C < DD) ? (NN + r1) : r1;
            float2 d0 = *(const float2*)&g_XW[(size_t)dr0 * DD + oc];
            float2 d1 = *(const float2*)&g_XW[(size_t)dr1 * DD + oc];
            acc[nj][0] += s0 * d0.x; acc[nj][1] += s0 * d0.y;
            acc[nj][2] += s1 * d1.x; acc[nj][3] += s1 * d1.y;
        }
    }
    float* Yp = g_Yp[blockIdx.z];
    #pragma unroll
    for (int nj = 0; nj < 16; ++nj) {
        int cc = nbg + nj * 8 + qp * 2;
        *(float2*)&Yp[(size_t)r0 * ZC + cc] = make_float2(acc[nj][0], acc[nj][1]);
        *(float2*)&Yp[(size_t)r1 * ZC + cc] = make_float2(acc[nj][2], acc[nj][3]);
    }
}

// ---------------------------------------------------------------------------
// K4: epilogue. h = s_i * (y0+y1+y2+y3), diag already folded. BN stats.
// grid 256 x 256, 4 slots/thread; ALL 16 partial loads issued up-front
// (MLP ~16/thread) before any arithmetic.
// ---------------------------------------------------------------------------
__global__ void k_epi(float* __restrict__ out) {
    __shared__ float sstat[2 * DD];
    int t = threadIdx.x;
    sstat[t] = 0.0f;
    __syncthreads();
    int base = blockIdx.x * 256 + t;            // 4 slots/thread, stride 65536
    int C = (base & 63) * 4;                    // column invariant across slots
    int oc = (C < DD) ? C : (C - DD);

    float4 y[4][4];
    float sv[4];
    #pragma unroll
    for (int sIt = 0; sIt < 4; ++sIt) {
        int i = (base + sIt * 65536) >> 6;
        #pragma unroll
        for (int z = 0; z < KSPLIT; ++z)
            y[sIt][z] = *(const float4*)&g_Yp[z][(size_t)i * ZC + C];
        sv[sIt] = g_s[i];
    }

    float lsum[4] = {0.f, 0.f, 0.f, 0.f};
    float lsq[4]  = {0.f, 0.f, 0.f, 0.f};
    #pragma unroll
    for (int sIt = 0; sIt < 4; ++sIt) {
        int i = (base + sIt * 65536) >> 6;
        float s = sv[sIt];
        float4 h;
        h.x = s * (y[sIt][0].x + y[sIt][1].x + y[sIt][2].x + y[sIt][3].x);
        h.y = s * (y[sIt][0].y + y[sIt][1].y + y[sIt][2].y + y[sIt][3].y);
        h.z = s * (y[sIt][0].z + y[sIt][1].z + y[sIt][2].z + y[sIt][3].z);
        h.w = s * (y[sIt][0].w + y[sIt][1].w + y[sIt][2].w + y[sIt][3].w);
        int orow = (C < DD) ? i : (NN + i);
        *(float4*)&out[(size_t)orow * DD + oc] = h;
        lsum[0] += h.x; lsum[1] += h.y; lsum[2] += h.z; lsum[3] += h.w;
        lsq[0] += h.x * h.x; lsq[1] += h.y * h.y; lsq[2] += h.z * h.z; lsq[3] += h.w * h.w;
    }
    #pragma unroll
    for (int q = 0; q < 4; ++q) {
        atomicAdd(&sstat[oc + q], lsum[q]);
        atomicAdd(&sstat[DD + oc + q], lsq[q]);
    }
    __syncthreads();
    atomicAdd(&g_stats[t], sstat[t]);
}

// ---------------------------------------------------------------------------
// K5: finalize BatchNorm (biased var) + ReLU, float4 per thread.
// ---------------------------------------------------------------------------
__global__ void k_bn(float* __restrict__ out,
                     const float* __restrict__ gamma,
                     const float* __restrict__ beta) {
    __shared__ float sscale[DD], sshift[DD];
    int t = threadIdx.x;
    if (t < DD) {
        float mean = g_stats[t] * (1.0f / (float)TWO_N);
        float var  = g_stats[DD + t] * (1.0f / (float)TWO_N) - mean * mean;
        float inv  = rsqrtf(var + 1e-5f);
        float g = gamma[t];
        sscale[t] = inv * g;
        sshift[t] = beta[t] - mean * inv * g;
    }
    __syncthreads();
    int idx = (blockIdx.x * 256 + t) * 4;
    int c = idx & (DD - 1);
    float4 v = *(float4*)&out[idx];
    v.x = fmaxf(v.x * sscale[c]     + sshift[c],     0.0f);
    v.y = fmaxf(v.y * sscale[c + 1] + sshift[c + 1], 0.0f);
    v.z = fmaxf(v.z * sscale[c + 2] + sshift[c + 2], 0.0f);
    v.w = fmaxf(v.w * sscale[c + 3] + sshift[c + 3], 0.0f);
    *(float4*)&out[idx] = v;
}

// ---------------------------------------------------------------------------
extern "C" void kernel_launch(void* const* d_in, const int* in_sizes, int n_in,
                              void* d_out, int out_size) {
    const float* x     = (const float*)d_in[0];   // [8192, 128]
    const float* A     = (const float*)d_in[1];   // [4096, 4096]
    const float* Wm    = (const float*)d_in[2];   // [128, 128]
    const float* gamma = (const float*)d_in[3];   // [128]
    const float* beta  = (const float*)d_in[4];   // [128]
    float* out = (float*)d_out;                   // [8192, 128]

    cudaFuncSetAttribute(k_gemm, cudaFuncAttributeMaxDynamicSharedMemorySize, SMEM_GEMM);
    cudaFuncSetAttribute(k_xwm,  cudaFuncAttributeMaxDynamicSharedMemorySize, SMEM_XWM);

    k_prep<<<NN, 128>>>(A);
    k_xwm <<<TWO_N / 128, 256, SMEM_XWM>>>(x, Wm);
    dim3 gg(NN / 128, 2, KSPLIT);
    k_gemm<<<gg, 256, SMEM_GEMM>>>();
    k_epi <<<256, 256>>>(out);
    k_bn  <<<(TWO_N * DD) / 1024, 256>>>(out, gamma, beta);
}

// round 16
// speedup vs baseline: 1.0979x; 1.0979x over previous
#include <cuda_runtime.h>
#include <cuda_fp16.h>
#include <cstdint>

#define NN    4096
#define DD    128
#define TWO_N 8192
#define ZC    256
#define KSPLIT 4
#define KPER  (NN / KSPLIT)      // 1024 per CTA
#define KC    64
#define NCHC  (KPER / KC)        // 16 chunks per CTA
#define NCH_ALL (NN / KC)        // 64 chunks total
#define BSTG  16384              // B stage: 64x128 fp16
#define STG   17408              // B + 1KB mask
#define STAGES 4
#define SMEM_GEMM (STAGES * STG) // 69632 -> 2 CTAs/SM
#define SMEM_XWM  65536          // x tile 32K + W tile 32K

// ------------------------- device scratch -------------------------
__device__ __align__(16) unsigned g_maskT[(size_t)NCH_ALL * NN * 2]; // 2 MB [chunk][row][2w]
__device__ __align__(16) __half g_Zh[(size_t)NN * ZC];               // 2 MB [K][N]
__device__ __align__(16) float g_XW[(size_t)TWO_N * DD];             // 4 MB
__device__ __align__(16) __half g_Yp[KSPLIT][(size_t)NN * ZC];       // 8 MB fp16 partials
__device__ float g_s[NN];
__device__ float g_stats[2 * DD];

// ------------------------- PTX helpers ----------------------------
__device__ __forceinline__ uint32_t smem_u32(const void* p) {
    uint32_t a;
    asm("{ .reg .u64 t; cvta.to.shared.u64 t, %1; cvt.u32.u64 %0, t; }" : "=r"(a) : "l"(p));
    return a;
}
#define CP16(dst, src) asm volatile("cp.async.cg.shared.global [%0], [%1], 16;" :: "r"(dst), "l"(src))
#define CP8(dst, src)  asm volatile("cp.async.ca.shared.global [%0], [%1], 8;"  :: "r"(dst), "l"(src))
#define CP_COMMIT()    asm volatile("cp.async.commit_group;" ::: "memory")
#define CP_WAITN(n)    asm volatile("cp.async.wait_group %0;" :: "n"(n) : "memory")

#define LDSM4(r, a)  asm volatile("ldmatrix.sync.aligned.m8n8.x4.shared.b16 {%0,%1,%2,%3}, [%4];" \
    : "=r"((r)[0]),"=r"((r)[1]),"=r"((r)[2]),"=r"((r)[3]) : "r"(a))
#define LDSM4T(r, a) asm volatile("ldmatrix.sync.aligned.m8n8.x4.trans.shared.b16 {%0,%1,%2,%3}, [%4];" \
    : "=r"((r)[0]),"=r"((r)[1]),"=r"((r)[2]),"=r"((r)[3]) : "r"(a))

#define MMA(d, a, b0_, b1_) asm volatile( \
    "mma.sync.aligned.m16n8k16.row.col.f32.f16.f16.f32 " \
    "{%0,%1,%2,%3},{%4,%5,%6,%7},{%8,%9},{%0,%1,%2,%3};" \
    : "+f"((d)[0]),"+f"((d)[1]),"+f"((d)[2]),"+f"((d)[3]) \
    : "r"((a)[0]),"r"((a)[1]),"r"((a)[2]),"r"((a)[3]), "r"(b0_), "r"(b1_))

// 2 bits -> packed fp16x2 (bit0 -> low half, bit1 -> high half), 1.0 or 0.0
__device__ __forceinline__ uint32_t lut2(unsigned e) {
    return ((e & 1u) ? 0x3C00u : 0u) | ((e & 2u) ? 0x3C000000u : 0u);
}
__device__ __forceinline__ uint32_t pack_h2(float a, float b) {
    return (uint32_t)__half_as_ushort(__float2half_rn(a))
         | ((uint32_t)__half_as_ushort(__float2half_rn(b)) << 16);
}

// ---------------------------------------------------------------------------
// K1: binarize A -> transposed bitmask [chunk][row][2 words]; rowsum -> s.
// ---------------------------------------------------------------------------
__global__ void k_prep(const float* __restrict__ A) {
    int row = blockIdx.x, t = threadIdx.x, w = t >> 5, l = t & 31;
    __shared__ int scnt[4];
    if (row == 0 && t < 128) { g_stats[t] = 0.0f; g_stats[128 + t] = 0.0f; }
    const float* ar = A + (size_t)row * NN;
    int cnt = 0;
    #pragma unroll 4
    for (int it = 0; it < 32; ++it) {
        float v = ar[it * 128 + t];
        bool b = (v > 0.0f);
        unsigned bal = __ballot_sync(0xffffffffu, b);
        cnt += b ? 1 : 0;
        if (l == 0) {
            int W = it * 4 + w;                      // 32-col word index 0..127
            g_maskT[((size_t)(W >> 1) * NN + row) * 2 + (W & 1)] = bal;
        }
    }
    #pragma unroll
    for (int o = 16; o; o >>= 1) cnt += __shfl_down_sync(0xffffffffu, cnt, o);
    if (l == 0) scnt[w] = cnt;
    __syncthreads();
    if (t == 0)
        g_s[row] = rsqrtf((float)(scnt[0] + scnt[1] + scnt[2] + scnt[3] + 1));
}

// ---------------------------------------------------------------------------
// K2: xw = x@W on tensor cores, fused Z build (round-13 proven).
// ---------------------------------------------------------------------------
__global__ void __launch_bounds__(256) k_xwm(const float* __restrict__ x,
                                             const float* __restrict__ W) {
    extern __shared__ char smem[];
    uint32_t sb = smem_u32(smem);          // [0,32768) x-tile, [32768,65536) W-tile
    int t = threadIdx.x, wid = t >> 5, lid = t & 31;
    int rbase = blockIdx.x * 128;

    #pragma unroll
    for (int p = 0; p < 16; ++p) {
        int idx = t + p * 256;
        int r = idx >> 5, k4 = idx & 31;
        float4 v = *(const float4*)&x[(size_t)(rbase + r) * DD + k4 * 4];
        uint2 pk = make_uint2(pack_h2(v.x, v.y), pack_h2(v.z, v.w));
        uint32_t off = (uint32_t)(r * 256 + (((k4 >> 1) ^ (r & 7)) << 4) + (k4 & 1) * 8);
        *(uint2*)(smem + off) = pk;
    }
    #pragma unroll
    for (int p = 0; p < 16; ++p) {
        int idx = t + p * 256;
        int k = idx >> 5, n4 = idx & 31;
        float4 v = *(const float4*)&W[(size_t)k * DD + n4 * 4];
        uint2 pk = make_uint2(pack_h2(v.x, v.y), pack_h2(v.z, v.w));
        uint32_t off = (uint32_t)(32768 + k * 256 + (((n4 >> 1) ^ (k & 7)) << 4) + (n4 & 1) * 8);
        *(uint2*)(smem + off) = pk;
    }
    __syncthreads();

    int m0 = wid * 16;
    float acc[16][4];
    #pragma unroll
    for (int nj = 0; nj < 16; ++nj)
        #pragma unroll
        for (int q = 0; q < 4; ++q) acc[nj][q] = 0.0f;

    #pragma unroll
    for (int kk = 0; kk < 8; ++kk) {
        uint32_t af[4];
        int arow = m0 + (lid & 15);
        int ach  = kk * 2 + (lid >> 4);
        LDSM4(af, sb + arow * 256 + ((ach ^ (arow & 7)) << 4));
        int kb = kk * 16 + (lid & 15);
        int cb = lid >> 4;
        #pragma unroll
        for (int g = 0; g < 4; ++g) {
            uint32_t bf[4][2];
            #pragma unroll
            for (int np = 0; np < 2; ++np) {
                int ch = g * 4 + np * 2 + cb;
                uint32_t r4[4];
                LDSM4T(r4, sb + 32768 + kb * 256 + ((ch ^ (kb & 7)) << 4));
                bf[np*2][0]=r4[0]; bf[np*2][1]=r4[1];
                bf[np*2+1][0]=r4[2]; bf[np*2+1][1]=r4[3];
            }
            #pragma unroll
            for (int nj = 0; nj < 4; ++nj)
                MMA(acc[g * 4 + nj], af, bf[nj][0], bf[nj][1]);
        }
    }

    int grp = lid >> 2, qp = lid & 3;
    int gr0 = rbase + m0 + grp;
    int gr1 = gr0 + 8;
    int top0 = (gr0 < NN);
    int j0 = top0 ? gr0 : (gr0 - NN);
    int j1 = top0 ? gr1 : (gr1 - NN);
    float s0 = g_s[j0], s1 = g_s[j1];
    int cof = top0 ? 0 : DD;
    #pragma unroll
    for (int nj = 0; nj < 16; ++nj) {
        int c = nj * 8 + qp * 2;
        *(float2*)&g_XW[(size_t)gr0 * DD + c] = make_float2(acc[nj][0], acc[nj][1]);
        *(float2*)&g_XW[(size_t)gr1 * DD + c] = make_float2(acc[nj][2], acc[nj][3]);
        *(uint32_t*)&g_Zh[(size_t)j0 * ZC + cof + c] = pack_h2(s0 * acc[nj][0], s0 * acc[nj][1]);
        *(uint32_t*)&g_Zh[(size_t)j1 * ZC + cof + c] = pack_h2(s1 * acc[nj][2], s1 * acc[nj][3]);
    }
}

// ---------------------------------------------------------------------------
// K3: GEMM partials (round-13 proven shape). grid (32, 2, 4): CTA 128x128,
// K-split/4 on grid.z. 8 warps, warp tile 16x128. 4-stage cp.async, one
// barrier per chunk, 2 CTAs/SM. Partials stored as fp16 (halved traffic).
// ---------------------------------------------------------------------------
__global__ void __launch_bounds__(256, 2) k_gemm() {
    extern __shared__ char smem[];
    uint32_t sb = smem_u32(smem);
    int t = threadIdx.x, wid = t >> 5, lid = t & 31;
    int m0 = wid * 16;
    int mbase = blockIdx.x * 128;
    int nbg   = blockIdx.y * 128;
    const __half* Bg = g_Zh + (size_t)(blockIdx.z * KPER) * ZC + nbg;
    const unsigned* Mg = g_maskT + ((size_t)(blockIdx.z * NCHC) * NN + mbase) * 2;

    auto issue = [&](int c) {
        if (c < NCHC) {
            uint32_t sa = sb + (c % STAGES) * STG;
            #pragma unroll
            for (int p = 0; p < 4; ++p) {            // B: 64x128 fp16, 256B rows
                int idx = t + p * 256;
                int k = idx >> 4, ch = idx & 15;
                uint32_t off = k * 256 + ((ch ^ (k & 7)) << 4);
                CP16(sa + off, (const char*)(Bg + (size_t)(c * KC + k) * ZC + ch * 8));
            }
            if (t < 128)                              // mask: 128 rows x 8B
                CP8(sa + BSTG + t * 8, (const char*)(Mg + (size_t)c * NN * 2 + t * 2));
        }
        CP_COMMIT();
    };

    float acc[16][4];
    #pragma unroll
    for (int nj = 0; nj < 16; ++nj)
        #pragma unroll
        for (int q = 0; q < 4; ++q) acc[nj][q] = 0.0f;

    issue(0); issue(1); issue(2);

    int ra = lid >> 2;
    int c0 = (lid & 3) * 2;

    for (int c = 0; c < NCHC; ++c) {
        CP_WAITN(2);                 // chunk c resident (<=2 groups pending)
        __syncthreads();             // all warps done with stage (c-1)%4
        issue(c + 3);                // refills stage (c+3)%4 == (c-1)%4
        uint32_t sa = sb + (c % STAGES) * STG;
        const uint2* maskS = (const uint2*)(smem + (c % STAGES) * STG + BSTG);

        uint2 mw0 = maskS[m0 + ra];      // row m0+ra of my strip
        uint2 mw1 = maskS[m0 + ra + 8];  // row m0+ra+8

        #pragma unroll
        for (int kk = 0; kk < 4; ++kk) {
            int kb = kk * 16 + (lid & 15);
            int cb = lid >> 4;
            int sh = ((kk & 1) << 4) + c0;
            unsigned ta = ((kk < 2) ? mw0.x : mw0.y) >> sh;
            unsigned tb = ((kk < 2) ? mw1.x : mw1.y) >> sh;
            uint32_t af[4];
            af[0] = lut2(ta & 3u);           // (ra,   c0..c0+1)
            af[1] = lut2(tb & 3u);           // (ra+8, c0..c0+1)
            af[2] = lut2((ta >> 8) & 3u);    // (ra,   c0+8..c0+9)
            af[3] = lut2((tb >> 8) & 3u);    // (ra+8, c0+8..c0+9)
            #pragma unroll
            for (int g = 0; g < 4; ++g) {            // 4 groups of 32 cols
                uint32_t bf[4][2];
                #pragma unroll
                for (int np = 0; np < 2; ++np) {
                    int ch = g * 4 + np * 2 + cb;    // 16B column-chunk index
                    uint32_t r4[4];
                    LDSM4T(r4, sa + kb * 256 + ((ch ^ (kb & 7)) << 4));
                    bf[np*2][0]=r4[0]; bf[np*2][1]=r4[1];
                    bf[np*2+1][0]=r4[2]; bf[np*2+1][1]=r4[3];
                }
                #pragma unroll
                for (int nj = 0; nj < 4; ++nj)
                    MMA(acc[g * 4 + nj], af, bf[nj][0], bf[nj][1]);
            }
        }
    }

    // write partial tile as fp16 (16 rows x 128 cols per warp)
    __half* Yp = g_Yp[blockIdx.z];
    int grp = lid >> 2, qp = lid & 3;
    int r0 = mbase + m0 + grp;
    int r1 = r0 + 8;
    #pragma unroll
    for (int nj = 0; nj < 16; ++nj) {
        int cc = nbg + nj * 8 + qp * 2;
        *(uint32_t*)&Yp[(size_t)r0 * ZC + cc] = pack_h2(acc[nj][0], acc[nj][1]);
        *(uint32_t*)&Yp[(size_t)r1 * ZC + cc] = pack_h2(acc[nj][2], acc[nj][3]);
    }
}

// ---------------------------------------------------------------------------
// K4: epilogue. Sum fp16 partials, s-scale + diag, write out, BN stats.
// grid 256 x 256, 4 slots/thread; all Yp + XW loads issued up-front.
// ---------------------------------------------------------------------------
__global__ void k_epi(float* __restrict__ out) {
    __shared__ float sstat[2 * DD];
    int t = threadIdx.x;
    sstat[t] = 0.0f;
    __syncthreads();
    int base = blockIdx.x * 256 + t;            // 4 slots/thread, stride 65536
    int C = (base & 63) * 4;                    // column invariant across slots
    int oc = (C < DD) ? C : (C - DD);

    uint2  yp[4][4];
    float4 dv[4];
    float  sv[4];
    #pragma unroll
    for (int sIt = 0; sIt < 4; ++sIt) {
        int i = (base + sIt * 65536) >> 6;
        #pragma unroll
        for (int z = 0; z < KSPLIT; ++z)
            yp[sIt][z] = *(const uint2*)&g_Yp[z][(size_t)i * ZC + C];
        int drow = (C < DD) ? (NN + i) : i;
        dv[sIt] = *(const float4*)&g_XW[(size_t)drow * DD + oc];
        sv[sIt] = g_s[i];
    }

    float lsum[4] = {0.f, 0.f, 0.f, 0.f};
    float lsq[4]  = {0.f, 0.f, 0.f, 0.f};
    #pragma unroll
    for (int sIt = 0; sIt < 4; ++sIt) {
        int i = (base + sIt * 65536) >> 6;
        float4 y = make_float4(0.f, 0.f, 0.f, 0.f);
        #pragma unroll
        for (int z = 0; z < KSPLIT; ++z) {
            float2 fa = __half22float2(*reinterpret_cast<const __half2*>(&yp[sIt][z].x));
            float2 fb = __half22float2(*reinterpret_cast<const __half2*>(&yp[sIt][z].y));
            y.x += fa.x; y.y += fa.y; y.z += fb.x; y.w += fb.y;
        }
        float s = sv[sIt], s2 = s * s;
        float4 h;
        h.x = s * y.x + s2 * dv[sIt].x;
        h.y = s * y.y + s2 * dv[sIt].y;
        h.z = s * y.z + s2 * dv[sIt].z;
        h.w = s * y.w + s2 * dv[sIt].w;
        int orow = (C < DD) ? i : (NN + i);
        *(float4*)&out[(size_t)orow * DD + oc] = h;
        lsum[0] += h.x; lsum[1] += h.y; lsum[2] += h.z; lsum[3] += h.w;
        lsq[0] += h.x * h.x; lsq[1] += h.y * h.y; lsq[2] += h.z * h.z; lsq[3] += h.w * h.w;
    }
    #pragma unroll
    for (int q = 0; q < 4; ++q) {
        atomicAdd(&sstat[oc + q], lsum[q]);
        atomicAdd(&sstat[DD + oc + q], lsq[q]);
    }
    __syncthreads();
    atomicAdd(&g_stats[t], sstat[t]);
}

// ---------------------------------------------------------------------------
// K5: finalize BatchNorm (biased var) + ReLU, float4 per thread.
// ---------------------------------------------------------------------------
__global__ void k_bn(float* __restrict__ out,
                     const float* __restrict__ gamma,
                     const float* __restrict__ beta) {
    __shared__ float sscale[DD], sshift[DD];
    int t = threadIdx.x;
    if (t < DD) {
        float mean = g_stats[t] * (1.0f / (float)TWO_N);
        float var  = g_stats[DD + t] * (1.0f / (float)TWO_N) - mean * mean;
        float inv  = rsqrtf(var + 1e-5f);
        float g = gamma[t];
        sscale[t] = inv * g;
        sshift[t] = beta[t] - mean * inv * g;
    }
    __syncthreads();
    int idx = (blockIdx.x * 256 + t) * 4;
    int c = idx & (DD - 1);
    float4 v = *(float4*)&out[idx];
    v.x = fmaxf(v.x * sscale[c]     + sshift[c],     0.0f);
    v.y = fmaxf(v.y * sscale[c + 1] + sshift[c + 1], 0.0f);
    v.z = fmaxf(v.z * sscale[c + 2] + sshift[c + 2], 0.0f);
    v.w = fmaxf(v.w * sscale[c + 3] + sshift[c + 3], 0.0f);
    *(float4*)&out[idx] = v;
}

// ---------------------------------------------------------------------------
extern "C" void kernel_launch(void* const* d_in, const int* in_sizes, int n_in,
                              void* d_out, int out_size) {
    const float* x     = (const float*)d_in[0];   // [8192, 128]
    const float* A     = (const float*)d_in[1];   // [4096, 4096]
    const float* Wm    = (const float*)d_in[2];   // [128, 128]
    const float* gamma = (const float*)d_in[3];   // [128]
    const float* beta  = (const float*)d_in[4];   // [128]
    float* out = (float*)d_out;                   // [8192, 128]

    cudaFuncSetAttribute(k_gemm, cudaFuncAttributeMaxDynamicSharedMemorySize, SMEM_GEMM);
    cudaFuncSetAttribute(k_xwm,  cudaFuncAttributeMaxDynamicSharedMemorySize, SMEM_XWM);

    k_prep<<<NN, 128>>>(A);
    k_xwm <<<TWO_N / 128, 256, SMEM_XWM>>>(x, Wm);
    dim3 gg(NN / 128, 2, KSPLIT);
    k_gemm<<<gg, 256, SMEM_GEMM>>>();
    k_epi <<<256, 256>>>(out);
    k_bn  <<<(TWO_N * DD) / 1024, 256>>>(out, gamma, beta);
}

// round 17
// speedup vs baseline: 1.1065x; 1.0078x over previous
#include <cuda_runtime.h>
#include <cuda_fp16.h>
#include <cstdint>

#define NN    4096
#define DD    128
#define TWO_N 8192
#define ZC    256
#define KSPLIT 4
#define KPER  (NN / KSPLIT)      // 1024 per CTA
#define KC    64
#define NCHC  (KPER / KC)        // 16 chunks per CTA
#define NCH_ALL (NN / KC)        // 64 chunks total
#define BSTG  16384              // B stage: 64x128 fp16
#define STG   17408              // B + 1KB mask
#define STAGES 4
#define SMEM_GEMM (STAGES * STG) // 69632 -> 2 CTAs/SM
#define SMEM_XWM  65536          // x tile 32K + W tile 32K
#define EPI_GRID 256

// ------------------------- device scratch -------------------------
__device__ __align__(16) unsigned g_maskT[(size_t)NCH_ALL * NN * 2]; // 2 MB [chunk][row][2w]
__device__ __align__(16) __half g_Zh[(size_t)NN * ZC];               // 2 MB [K][N]
__device__ __align__(16) float g_XW[(size_t)TWO_N * DD];             // 4 MB
__device__ __align__(16) __half g_Yp[KSPLIT][(size_t)NN * ZC];       // 8 MB fp16 partials
__device__ float g_s[NN];
__device__ float g_stats[2 * DD];
__device__ unsigned g_ctr;

// ------------------------- PTX helpers ----------------------------
__device__ __forceinline__ uint32_t smem_u32(const void* p) {
    uint32_t a;
    asm("{ .reg .u64 t; cvta.to.shared.u64 t, %1; cvt.u32.u64 %0, t; }" : "=r"(a) : "l"(p));
    return a;
}
#define CP16(dst, src) asm volatile("cp.async.cg.shared.global [%0], [%1], 16;" :: "r"(dst), "l"(src))
#define CP8(dst, src)  asm volatile("cp.async.ca.shared.global [%0], [%1], 8;"  :: "r"(dst), "l"(src))
#define CP_COMMIT()    asm volatile("cp.async.commit_group;" ::: "memory")
#define CP_WAITN(n)    asm volatile("cp.async.wait_group %0;" :: "n"(n) : "memory")

#define LDSM4(r, a)  asm volatile("ldmatrix.sync.aligned.m8n8.x4.shared.b16 {%0,%1,%2,%3}, [%4];" \
    : "=r"((r)[0]),"=r"((r)[1]),"=r"((r)[2]),"=r"((r)[3]) : "r"(a))
#define LDSM4T(r, a) asm volatile("ldmatrix.sync.aligned.m8n8.x4.trans.shared.b16 {%0,%1,%2,%3}, [%4];" \
    : "=r"((r)[0]),"=r"((r)[1]),"=r"((r)[2]),"=r"((r)[3]) : "r"(a))

#define MMA(d, a, b0_, b1_) asm volatile( \
    "mma.sync.aligned.m16n8k16.row.col.f32.f16.f16.f32 " \
    "{%0,%1,%2,%3},{%4,%5,%6,%7},{%8,%9},{%0,%1,%2,%3};" \
    : "+f"((d)[0]),"+f"((d)[1]),"+f"((d)[2]),"+f"((d)[3]) \
    : "r"((a)[0]),"r"((a)[1]),"r"((a)[2]),"r"((a)[3]), "r"(b0_), "r"(b1_))

// 2 bits -> packed fp16x2 (bit0 -> low half, bit1 -> high half), 1.0 or 0.0
__device__ __forceinline__ uint32_t lut2(unsigned e) {
    return ((e & 1u) ? 0x3C00u : 0u) | ((e & 2u) ? 0x3C000000u : 0u);
}
__device__ __forceinline__ uint32_t pack_h2(float a, float b) {
    return (uint32_t)__half_as_ushort(__float2half_rn(a))
         | ((uint32_t)__half_as_ushort(__float2half_rn(b)) << 16);
}

// ---------------------------------------------------------------------------
// K1: binarize A -> transposed bitmask [chunk][row][2 words]; rowsum -> s.
// Also resets g_stats and the epi arrival counter (graph-replay safe).
// ---------------------------------------------------------------------------
__global__ void k_prep(const float* __restrict__ A) {
    int row = blockIdx.x, t = threadIdx.x, w = t >> 5, l = t & 31;
    __shared__ int scnt[4];
    if (row == 0 && t < 128) { g_stats[t] = 0.0f; g_stats[128 + t] = 0.0f; }
    if (row == 0 && t == 0) g_ctr = 0u;
    const float* ar = A + (size_t)row * NN;
    int cnt = 0;
    #pragma unroll 4
    for (int it = 0; it < 32; ++it) {
        float v = ar[it * 128 + t];
        bool b = (v > 0.0f);
        unsigned bal = __ballot_sync(0xffffffffu, b);
        cnt += b ? 1 : 0;
        if (l == 0) {
            int W = it * 4 + w;                      // 32-col word index 0..127
            g_maskT[((size_t)(W >> 1) * NN + row) * 2 + (W & 1)] = bal;
        }
    }
    #pragma unroll
    for (int o = 16; o; o >>= 1) cnt += __shfl_down_sync(0xffffffffu, cnt, o);
    if (l == 0) scnt[w] = cnt;
    __syncthreads();
    if (t == 0)
        g_s[row] = rsqrtf((float)(scnt[0] + scnt[1] + scnt[2] + scnt[3] + 1));
}

// ---------------------------------------------------------------------------
// K2: xw = x@W on tensor cores, fused Z build (round-13 proven).
// ---------------------------------------------------------------------------
__global__ void __launch_bounds__(256) k_xwm(const float* __restrict__ x,
                                             const float* __restrict__ W) {
    extern __shared__ char smem[];
    uint32_t sb = smem_u32(smem);          // [0,32768) x-tile, [32768,65536) W-tile
    int t = threadIdx.x, wid = t >> 5, lid = t & 31;
    int rbase = blockIdx.x * 128;

    #pragma unroll
    for (int p = 0; p < 16; ++p) {
        int idx = t + p * 256;
        int r = idx >> 5, k4 = idx & 31;
        float4 v = *(const float4*)&x[(size_t)(rbase + r) * DD + k4 * 4];
        uint2 pk = make_uint2(pack_h2(v.x, v.y), pack_h2(v.z, v.w));
        uint32_t off = (uint32_t)(r * 256 + (((k4 >> 1) ^ (r & 7)) << 4) + (k4 & 1) * 8);
        *(uint2*)(smem + off) = pk;
    }
    #pragma unroll
    for (int p = 0; p < 16; ++p) {
        int idx = t + p * 256;
        int k = idx >> 5, n4 = idx & 31;
        float4 v = *(const float4*)&W[(size_t)k * DD + n4 * 4];
        uint2 pk = make_uint2(pack_h2(v.x, v.y), pack_h2(v.z, v.w));
        uint32_t off = (uint32_t)(32768 + k * 256 + (((n4 >> 1) ^ (k & 7)) << 4) + (n4 & 1) * 8);
        *(uint2*)(smem + off) = pk;
    }
    __syncthreads();

    int m0 = wid * 16;
    float acc[16][4];
    #pragma unroll
    for (int nj = 0; nj < 16; ++nj)
        #pragma unroll
        for (int q = 0; q < 4; ++q) acc[nj][q] = 0.0f;

    #pragma unroll
    for (int kk = 0; kk < 8; ++kk) {
        uint32_t af[4];
        int arow = m0 + (lid & 15);
        int ach  = kk * 2 + (lid >> 4);
        LDSM4(af, sb + arow * 256 + ((ach ^ (arow & 7)) << 4));
        int kb = kk * 16 + (lid & 15);
        int cb = lid >> 4;
        #pragma unroll
        for (int g = 0; g < 4; ++g) {
            uint32_t bf[4][2];
            #pragma unroll
            for (int np = 0; np < 2; ++np) {
                int ch = g * 4 + np * 2 + cb;
                uint32_t r4[4];
                LDSM4T(r4, sb + 32768 + kb * 256 + ((ch ^ (kb & 7)) << 4));
                bf[np*2][0]=r4[0]; bf[np*2][1]=r4[1];
                bf[np*2+1][0]=r4[2]; bf[np*2+1][1]=r4[3];
            }
            #pragma unroll
            for (int nj = 0; nj < 4; ++nj)
                MMA(acc[g * 4 + nj], af, bf[nj][0], bf[nj][1]);
        }
    }

    int grp = lid >> 2, qp = lid & 3;
    int gr0 = rbase + m0 + grp;
    int gr1 = gr0 + 8;
    int top0 = (gr0 < NN);
    int j0 = top0 ? gr0 : (gr0 - NN);
    int j1 = top0 ? gr1 : (gr1 - NN);
    float s0 = g_s[j0], s1 = g_s[j1];
    int cof = top0 ? 0 : DD;
    #pragma unroll
    for (int nj = 0; nj < 16; ++nj) {
        int c = nj * 8 + qp * 2;
        *(float2*)&g_XW[(size_t)gr0 * DD + c] = make_float2(acc[nj][0], acc[nj][1]);
        *(float2*)&g_XW[(size_t)gr1 * DD + c] = make_float2(acc[nj][2], acc[nj][3]);
        *(uint32_t*)&g_Zh[(size_t)j0 * ZC + cof + c] = pack_h2(s0 * acc[nj][0], s0 * acc[nj][1]);
        *(uint32_t*)&g_Zh[(size_t)j1 * ZC + cof + c] = pack_h2(s1 * acc[nj][2], s1 * acc[nj][3]);
    }
}

// ---------------------------------------------------------------------------
// K3: GEMM partials (round-13 proven shape). grid (32, 2, 4): CTA 128x128,
// K-split/4 on grid.z. 8 warps, warp tile 16x128. 4-stage cp.async, one
// barrier per chunk, 2 CTAs/SM. Partials stored as fp16.
// ---------------------------------------------------------------------------
__global__ void __launch_bounds__(256, 2) k_gemm() {
    extern __shared__ char smem[];
    uint32_t sb = smem_u32(smem);
    int t = threadIdx.x, wid = t >> 5, lid = t & 31;
    int m0 = wid * 16;
    int mbase = blockIdx.x * 128;
    int nbg   = blockIdx.y * 128;
    const __half* Bg = g_Zh + (size_t)(blockIdx.z * KPER) * ZC + nbg;
    const unsigned* Mg = g_maskT + ((size_t)(blockIdx.z * NCHC) * NN + mbase) * 2;

    auto issue = [&](int c) {
        if (c < NCHC) {
            uint32_t sa = sb + (c % STAGES) * STG;
            #pragma unroll
            for (int p = 0; p < 4; ++p) {            // B: 64x128 fp16, 256B rows
                int idx = t + p * 256;
                int k = idx >> 4, ch = idx & 15;
                uint32_t off = k * 256 + ((ch ^ (k & 7)) << 4);
                CP16(sa + off, (const char*)(Bg + (size_t)(c * KC + k) * ZC + ch * 8));
            }
            if (t < 128)                              // mask: 128 rows x 8B
                CP8(sa + BSTG + t * 8, (const char*)(Mg + (size_t)c * NN * 2 + t * 2));
        }
        CP_COMMIT();
    };

    float acc[16][4];
    #pragma unroll
    for (int nj = 0; nj < 16; ++nj)
        #pragma unroll
        for (int q = 0; q < 4; ++q) acc[nj][q] = 0.0f;

    issue(0); issue(1); issue(2);

    int ra = lid >> 2;
    int c0 = (lid & 3) * 2;

    for (int c = 0; c < NCHC; ++c) {
        CP_WAITN(2);                 // chunk c resident (<=2 groups pending)
        __syncthreads();             // all warps done with stage (c-1)%4
        issue(c + 3);                // refills stage (c+3)%4 == (c-1)%4
        uint32_t sa = sb + (c % STAGES) * STG;
        const uint2* maskS = (const uint2*)(smem + (c % STAGES) * STG + BSTG);

        uint2 mw0 = maskS[m0 + ra];      // row m0+ra of my strip
        uint2 mw1 = maskS[m0 + ra + 8];  // row m0+ra+8

        #pragma unroll
        for (int kk = 0; kk < 4; ++kk) {
            int kb = kk * 16 + (lid & 15);
            int cb = lid >> 4;
            int sh = ((kk & 1) << 4) + c0;
            unsigned ta = ((kk < 2) ? mw0.x : mw0.y) >> sh;
            unsigned tb = ((kk < 2) ? mw1.x : mw1.y) >> sh;
            uint32_t af[4];
            af[0] = lut2(ta & 3u);           // (ra,   c0..c0+1)
            af[1] = lut2(tb & 3u);           // (ra+8, c0..c0+1)
            af[2] = lut2((ta >> 8) & 3u);    // (ra,   c0+8..c0+9)
            af[3] = lut2((tb >> 8) & 3u);    // (ra+8, c0+8..c0+9)
            #pragma unroll
            for (int g = 0; g < 4; ++g) {            // 4 groups of 32 cols
                uint32_t bf[4][2];
                #pragma unroll
                for (int np = 0; np < 2; ++np) {
                    int ch = g * 4 + np * 2 + cb;    // 16B column-chunk index
                    uint32_t r4[4];
                    LDSM4T(r4, sa + kb * 256 + ((ch ^ (kb & 7)) << 4));
                    bf[np*2][0]=r4[0]; bf[np*2][1]=r4[1];
                    bf[np*2+1][0]=r4[2]; bf[np*2+1][1]=r4[3];
                }
                #pragma unroll
                for (int nj = 0; nj < 4; ++nj)
                    MMA(acc[g * 4 + nj], af, bf[nj][0], bf[nj][1]);
            }
        }
    }

    // write partial tile as fp16 (16 rows x 128 cols per warp)
    __half* Yp = g_Yp[blockIdx.z];
    int grp = lid >> 2, qp = lid & 3;
    int r0 = mbase + m0 + grp;
    int r1 = r0 + 8;
    #pragma unroll
    for (int nj = 0; nj < 16; ++nj) {
        int cc = nbg + nj * 8 + qp * 2;
        *(uint32_t*)&Yp[(size_t)r0 * ZC + cc] = pack_h2(acc[nj][0], acc[nj][1]);
        *(uint32_t*)&Yp[(size_t)r1 * ZC + cc] = pack_h2(acc[nj][2], acc[nj][3]);
    }
}

// ---------------------------------------------------------------------------
// K4: fused epilogue + BatchNorm + ReLU. grid 256 x 256, 4 slots/thread.
// Phase 1: sum fp16 partials + diag -> h (registers), BN stats via atomics.
// Phase 2: grid-wide arrival counter; after all 256 CTAs arrive, compute
// scale/shift from g_stats and apply BN+ReLU to register-resident h.
// All 256 CTAs are co-resident (capacity ~8 CTAs/SM) -> spin is safe.
// ---------------------------------------------------------------------------
__global__ void __launch_bounds__(256) k_epi(float* __restrict__ out,
                                             const float* __restrict__ gamma,
                                             const float* __restrict__ beta) {
    __shared__ float sstat[2 * DD];
    __shared__ float sscale[DD], sshift[DD];
    int t = threadIdx.x;
    sstat[t] = 0.0f;
    __syncthreads();
    int base = blockIdx.x * 256 + t;            // 4 slots/thread, stride 65536
    int C = (base & 63) * 4;                    // column invariant across slots
    int oc = (C < DD) ? C : (C - DD);

    uint2  yp[4][4];
    float4 dv[4];
    float  sv[4];
    #pragma unroll
    for (int sIt = 0; sIt < 4; ++sIt) {
        int i = (base + sIt * 65536) >> 6;
        #pragma unroll
        for (int z = 0; z < KSPLIT; ++z)
            yp[sIt][z] = *(const uint2*)&g_Yp[z][(size_t)i * ZC + C];
        int drow = (C < DD) ? (NN + i) : i;
        dv[sIt] = *(const float4*)&g_XW[(size_t)drow * DD + oc];
        sv[sIt] = g_s[i];
    }

    float4 h[4];
    float lsum[4] = {0.f, 0.f, 0.f, 0.f};
    float lsq[4]  = {0.f, 0.f, 0.f, 0.f};
    #pragma unroll
    for (int sIt = 0; sIt < 4; ++sIt) {
        float4 y = make_float4(0.f, 0.f, 0.f, 0.f);
        #pragma unroll
        for (int z = 0; z < KSPLIT; ++z) {
            float2 fa = __half22float2(*reinterpret_cast<const __half2*>(&yp[sIt][z].x));
            float2 fb = __half22float2(*reinterpret_cast<const __half2*>(&yp[sIt][z].y));
            y.x += fa.x; y.y += fa.y; y.z += fb.x; y.w += fb.y;
        }
        float s = sv[sIt], s2 = s * s;
        h[sIt].x = s * y.x + s2 * dv[sIt].x;
        h[sIt].y = s * y.y + s2 * dv[sIt].y;
        h[sIt].z = s * y.z + s2 * dv[sIt].z;
        h[sIt].w = s * y.w + s2 * dv[sIt].w;
        lsum[0] += h[sIt].x; lsum[1] += h[sIt].y; lsum[2] += h[sIt].z; lsum[3] += h[sIt].w;
        lsq[0] += h[sIt].x * h[sIt].x; lsq[1] += h[sIt].y * h[sIt].y;
        lsq[2] += h[sIt].z * h[sIt].z; lsq[3] += h[sIt].w * h[sIt].w;
    }
    #pragma unroll
    for (int q = 0; q < 4; ++q) {
        atomicAdd(&sstat[oc + q], lsum[q]);
        atomicAdd(&sstat[DD + oc + q], lsq[q]);
    }
    __syncthreads();
    atomicAdd(&g_stats[t], sstat[t]);

    // ---- grid-wide sync: all stats globally visible, then all CTAs proceed
    __threadfence();
    __syncthreads();
    if (t == 0) {
        atomicAdd(&g_ctr, 1u);
        while (*(volatile unsigned*)&g_ctr < (unsigned)EPI_GRID) {}
    }
    __syncthreads();

    if (t < DD) {
        float mean = __ldcg(&g_stats[t]) * (1.0f / (float)TWO_N);
        float var  = __ldcg(&g_stats[DD + t]) * (1.0f / (float)TWO_N) - mean * mean;
        float inv  = rsqrtf(var + 1e-5f);
        float g = gamma[t];
        sscale[t] = inv * g;
        sshift[t] = beta[t] - mean * inv * g;
    }
    __syncthreads();

    float sc0 = sscale[oc],     sh0 = sshift[oc];
    float sc1 = sscale[oc + 1], sh1 = sshift[oc + 1];
    float sc2 = sscale[oc + 2], sh2 = sshift[oc + 2];
    float sc3 = sscale[oc + 3], sh3 = sshift[oc + 3];
    #pragma unroll
    for (int sIt = 0; sIt < 4; ++sIt) {
        int i = (base + sIt * 65536) >> 6;
        int orow = (C < DD) ? i : (NN + i);
        float4 v;
        v.x = fmaxf(h[sIt].x * sc0 + sh0, 0.0f);
        v.y = fmaxf(h[sIt].y * sc1 + sh1, 0.0f);
        v.z = fmaxf(h[sIt].z * sc2 + sh2, 0.0f);
        v.w = fmaxf(h[sIt].w * sc3 + sh3, 0.0f);
        *(float4*)&out[(size_t)orow * DD + oc] = v;
    }
}

// ---------------------------------------------------------------------------
extern "C" void kernel_launch(void* const* d_in, const int* in_sizes, int n_in,
                              void* d_out, int out_size) {
    const float* x     = (const float*)d_in[0];   // [8192, 128]
    const float* A     = (const float*)d_in[1];   // [4096, 4096]
    const float* Wm    = (const float*)d_in[2];   // [128, 128]
    const float* gamma = (const float*)d_in[3];   // [128]
    const float* beta  = (const float*)d_in[4];   // [128]
    float* out = (float*)d_out;                   // [8192, 128]

    cudaFuncSetAttribute(k_gemm, cudaFuncAttributeMaxDynamicSharedMemorySize, SMEM_GEMM);
    cudaFuncSetAttribute(k_xwm,  cudaFuncAttributeMaxDynamicSharedMemorySize, SMEM_XWM);

    k_prep<<<NN, 128>>>(A);
    k_xwm <<<TWO_N / 128, 256, SMEM_XWM>>>(x, Wm);
    dim3 gg(NN / 128, 2, KSPLIT);
    k_gemm<<<gg, 256, SMEM_GEMM>>>();
    k_epi <<<EPI_GRID, 256>>>(out, gamma, beta);
}